// round 6
// baseline (speedup 1.0000x reference)
#include <cuda_runtime.h>
#include <cstdint>

// 2-layer LSTM (B=4096, T=256, D=4, H=64) + FC, fp32.
// Register-tiled smem GEMM per timestep, fused in-register cell update,
// ONE barrier/step. This revision targets codegen quality:
//   - 32-bit shared addressing: ld.shared.v2.u64 [r32 + imm], all row/k
//     offsets folded into immediates (was: 16x 64-bit generic pointers)
//   - two-phase thread tile (4 gates x 2 elems twice): halves live
//     accumulators/temps; phase-A activations (MUFU tanh) get scheduled
//     into phase-B's FMA stream
//   - fma.rn.f32x2 throughout; XOR bank swizzle unchanged from R5.

#define TT    256
#define HD    64
#define GD    256
#define EC    32
#define NT    512
#define ROWB  512
#define V_OFF 131072
#define VBUF  16384
#define SM_TOTAL 196608

typedef unsigned long long u64;

__device__ float g_h1[(size_t)4096 * TT * HD];

static __device__ __forceinline__ uint32_t s32(const void* p) {
    uint32_t a;
    asm("{.reg .u64 t; cvta.to.shared.u64 t,%1; cvt.u32.u64 %0,t;}"
        : "=r"(a) : "l"(p));
    return a;
}
static __device__ __forceinline__ u64 pk2(float lo, float hi) {
    u64 r; asm("mov.b64 %0,{%1,%2};" : "=l"(r) : "f"(lo), "f"(hi)); return r;
}
static __device__ __forceinline__ void up2(u64 v, float& lo, float& hi) {
    asm("mov.b64 {%0,%1},%2;" : "=f"(lo), "=f"(hi) : "l"(v));
}
static __device__ __forceinline__ u64 f2(u64 a, u64 b, u64 c) {
    u64 d; asm("fma.rn.f32x2 %0,%1,%2,%3;" : "=l"(d) : "l"(a), "l"(b), "l"(c));
    return d;
}
static __device__ __forceinline__ float tanha(float x) {
    float r; asm("tanh.approx.f32 %0, %1;" : "=f"(r) : "f"(x)); return r;
}
static __device__ __forceinline__ float sigt(float x) {
    return fmaf(0.5f, tanha(0.5f * x), 0.5f);
}

// 16B shared load -> two u64 (natural f32x2 operands). [r32 + const-imm].
#define LDSV2(d0, d1, addr, imm)                                              \
    asm volatile("ld.shared.v2.u64 {%0,%1},[%2+%3];"                          \
                 : "=l"(d0), "=l"(d1) : "r"(addr), "n"(imm))
#define STS32(addr, imm, val)                                                 \
    asm volatile("st.shared.f32 [%0+%1], %2;" :: "r"(addr), "n"(imm), "f"(val))

// One 4-k chunk for 4 gates x 2 elems: 6 LDS.128 -> 16 FFMA2.
// Gate rows at +0/+32768/+65536/+98304 (64*ROWB apart); elem rows at +512.
#define GEMM_P(BB, A128, ACC, EOFF)                                           \
    do {                                                                      \
        u64 w0l,w0h,w1l,w1h,w2l,w2h,w3l,w3h,x0l,x0h,x1l,x1h;                  \
        LDSV2(w0l, w0h, wa[BB], (A128));                                      \
        LDSV2(w1l, w1h, wa[BB], (A128) + 32768);                              \
        LDSV2(w2l, w2h, wa[BB], (A128) + 65536);                              \
        LDSV2(w3l, w3h, wa[BB], (A128) + 98304);                              \
        LDSV2(x0l, x0h, va[BB], (A128) + (EOFF));                             \
        LDSV2(x1l, x1h, va[BB], (A128) + (EOFF) + 512);                       \
        ACC[0][0]=f2(w0l,x0l,ACC[0][0]); ACC[0][0]=f2(w0h,x0h,ACC[0][0]);     \
        ACC[0][1]=f2(w0l,x1l,ACC[0][1]); ACC[0][1]=f2(w0h,x1h,ACC[0][1]);     \
        ACC[1][0]=f2(w1l,x0l,ACC[1][0]); ACC[1][0]=f2(w1h,x0h,ACC[1][0]);     \
        ACC[1][1]=f2(w1l,x1l,ACC[1][1]); ACC[1][1]=f2(w1h,x1h,ACC[1][1]);     \
        ACC[2][0]=f2(w2l,x0l,ACC[2][0]); ACC[2][0]=f2(w2h,x0h,ACC[2][0]);     \
        ACC[2][1]=f2(w2l,x1l,ACC[2][1]); ACC[2][1]=f2(w2h,x1h,ACC[2][1]);     \
        ACC[3][0]=f2(w3l,x0l,ACC[3][0]); ACC[3][0]=f2(w3h,x0h,ACC[3][0]);     \
        ACC[3][1]=f2(w3l,x1l,ACC[3][1]); ACC[3][1]=f2(w3h,x1h,ACC[3][1]);     \
    } while (0)

#define GEMM_G(A128, ACC, EOFF)                                               \
    do {                                                                      \
        GEMM_P(0, A128, ACC, EOFF); GEMM_P(1, A128, ACC, EOFF);               \
        GEMM_P(2, A128, ACC, EOFF); GEMM_P(3, A128, ACC, EOFF);               \
        GEMM_P(4, A128, ACC, EOFF); GEMM_P(5, A128, ACC, EOFF);               \
        GEMM_P(6, A128, ACC, EOFF); GEMM_P(7, A128, ACC, EOFF);               \
    } while (0)

#define ACC_INIT(ACC)                                                         \
    do {                                                                      \
        _Pragma("unroll")                                                     \
        for (int gi = 0; gi < 4; gi++) {                                      \
            ACC[gi][0] = pk2(bias[gi], 0.f);                                  \
            ACC[gi][1] = pk2(bias[gi], 0.f);                                  \
        }                                                                     \
    } while (0)

#define UPDATE_P(ACC, EI, CI, HOUT)                                           \
    do {                                                                      \
        float glo, ghi, vi, vf, vg, vo;                                       \
        up2(ACC[0][EI], glo, ghi); vi = glo + ghi;                            \
        up2(ACC[1][EI], glo, ghi); vf = glo + ghi;                            \
        up2(ACC[2][EI], glo, ghi); vg = glo + ghi;                            \
        up2(ACC[3][EI], glo, ghi); vo = glo + ghi;                            \
        c[CI] = sigt(vf) * c[CI] + sigt(vi) * tanha(vg);                      \
        HOUT = sigt(vo) * tanha(c[CI]);                                       \
    } while (0)

// ---------------------------------------------------------------------------
// Layer 1 + FC
// ---------------------------------------------------------------------------
__global__ void __launch_bounds__(NT, 1) lstm_l1(
    const float* __restrict__ Wih, const float* __restrict__ Whh,
    const float* __restrict__ bih, const float* __restrict__ bhh,
    const float* __restrict__ Wfc, const float* __restrict__ bfc,
    float* __restrict__ out)
{
    extern __shared__ char sm[];
    const int tid = threadIdx.x;
    const int b0  = blockIdx.x * EC;
    const int w   = tid >> 5, l = tid & 31;
    const int j   = (w & 7) * 8 + (l & 7);
    const int eb  = (w >> 3) * 4 + ((l >> 3) & 3);
    const int e0  = eb * 4;
    const int swW = j & 7, swV = eb & 7;

    for (int i = tid; i < GD * 32; i += NT) {
        int g = i >> 5, kc = i & 31, k = kc * 4;
        const float* src = (k < HD) ? (Wih + g * HD + k) : (Whh + g * HD + (k - HD));
        float4 v = *(const float4*)src;
        *(float4*)(sm + g * ROWB + ((kc ^ (g & 7)) << 4)) = v;
    }

    const int ue  = tid >> 4;
    const int uj  = (tid & 15) << 2;
    const int swU = (ue >> 2) & 7;
    const float* h1p = g_h1 + ((size_t)(b0 + ue) * TT) * HD + uj;

    {
        float4 h10 = *(const float4*)h1p;
        *(float4*)(sm + V_OFF + ue * ROWB + (((uj >> 2) ^ swU) << 4)) = h10;
        *(float4*)(sm + V_OFF + ue * ROWB + (((16 + (uj >> 2)) ^ swU) << 4)) =
            make_float4(0.f, 0.f, 0.f, 0.f);
    }

    float bias[4];
#pragma unroll
    for (int gi = 0; gi < 4; gi++) bias[gi] = bih[j + 64 * gi] + bhh[j + 64 * gi];

    const uint32_t smb = s32(sm);
    uint32_t wa[8], va[8];
#pragma unroll
    for (int b = 0; b < 8; b++) {
        wa[b] = smb + j * ROWB + ((b ^ swW) << 4);
        va[b] = smb + V_OFF + e0 * ROWB + ((b ^ swV) << 4);
    }
    const int colH = ((((16 + (j >> 2)) ^ swV) << 4)) + ((j & 3) << 2);
    uint32_t hw = smb + V_OFF + VBUF + e0 * ROWB + colH;
    char* pw = sm + V_OFF + VBUF + ue * ROWB + (((uj >> 2) ^ swU) << 4);
    int vflip = VBUF, wrflip = -VBUF;

    float c[4] = {0.f, 0.f, 0.f, 0.f};
    __syncthreads();

    for (int s = 0; s < TT; s++) {
        float4 pin = make_float4(0.f, 0.f, 0.f, 0.f);
        if (s + 1 < TT) pin = *(const float4*)(h1p + (size_t)(s + 1) * HD);

        u64 A0[4][2];
        ACC_INIT(A0);
        GEMM_G(0, A0, 0); GEMM_G(128, A0, 0);
        GEMM_G(256, A0, 0); GEMM_G(384, A0, 0);

        u64 A1[4][2];
        ACC_INIT(A1);
        GEMM_G(0, A1, 1024); GEMM_G(128, A1, 1024);
        GEMM_G(256, A1, 1024); GEMM_G(384, A1, 1024);

        float h0, h1v, h2, h3;
        UPDATE_P(A0, 0, 0, h0);  UPDATE_P(A0, 1, 1, h1v);
        UPDATE_P(A1, 0, 2, h2);  UPDATE_P(A1, 1, 3, h3);
        STS32(hw, 0, h0);    STS32(hw, 512, h1v);
        STS32(hw, 1024, h2); STS32(hw, 1536, h3);
        *(float4*)pw = pin;
        __syncthreads();

#pragma unroll
        for (int b = 0; b < 8; b++) va[b] += vflip;
        hw += wrflip; pw += wrflip;
        vflip = -vflip; wrflip = -wrflip;
    }

    // final h (t=TT-1) is in buffer 0 (V_OFF). Fused FC.
    float4 hf = *(const float4*)(sm + V_OFF + ue * ROWB +
                                 (((16 + (uj >> 2)) ^ swU) << 4));
    const float4 wfc = *(const float4*)(Wfc + uj);
    float p = hf.x * wfc.x + hf.y * wfc.y + hf.z * wfc.z + hf.w * wfc.w;
    p += __shfl_xor_sync(0xffffffffu, p, 8);
    p += __shfl_xor_sync(0xffffffffu, p, 4);
    p += __shfl_xor_sync(0xffffffffu, p, 2);
    p += __shfl_xor_sync(0xffffffffu, p, 1);
    if ((tid & 15) == 0) out[b0 + ue] = p + bfc[0];
}

// ---------------------------------------------------------------------------
// Layer 0: x[B,T,4] -> h1.  K chunks: 0 (x, D=4) + 1..16 (h).
// ---------------------------------------------------------------------------
__global__ void __launch_bounds__(NT, 1) lstm_l0(
    const float* __restrict__ x, const float* __restrict__ Wih,
    const float* __restrict__ Whh, const float* __restrict__ bih,
    const float* __restrict__ bhh)
{
    extern __shared__ char sm[];
    const int tid = threadIdx.x;
    const int b0  = blockIdx.x * EC;
    const int w   = tid >> 5, l = tid & 31;
    const int j   = (w & 7) * 8 + (l & 7);
    const int eb  = (w >> 3) * 4 + ((l >> 3) & 3);
    const int e0  = eb * 4;
    const int swW = j & 7, swV = eb & 7;

    for (int i = tid; i < GD * 32; i += NT) {
        int g = i >> 5, kc = i & 31;
        if (kc < 17) {
            float4 v;
            if (kc == 0) v = *(const float4*)(Wih + g * 4);
            else         v = *(const float4*)(Whh + g * HD + (kc * 4 - 4));
            *(float4*)(sm + g * ROWB + ((kc ^ (g & 7)) << 4)) = v;
        }
    }

    const int ue  = tid >> 4;
    const int uj  = (tid & 15) << 2;
    const int swU = (ue >> 2) & 7;
    *(float4*)(sm + V_OFF + ue * ROWB + (((1 + (uj >> 2)) ^ swU) << 4)) =
        make_float4(0.f, 0.f, 0.f, 0.f);
    const float* xp = 0;
    if (tid < 32) {
        xp = x + (size_t)(b0 + tid) * TT * 4;
        *(float4*)(sm + V_OFF + tid * ROWB + (((tid >> 2) & 7) << 4)) =
            *(const float4*)xp;
    }

    float bias[4];
#pragma unroll
    for (int gi = 0; gi < 4; gi++) bias[gi] = bih[j + 64 * gi] + bhh[j + 64 * gi];

    const uint32_t smb = s32(sm);
    uint32_t wa[8], va[8];
#pragma unroll
    for (int b = 0; b < 8; b++) {
        wa[b] = smb + j * ROWB + ((b ^ swW) << 4);
        va[b] = smb + V_OFF + e0 * ROWB + ((b ^ swV) << 4);
    }
    const int colH = ((((1 + (j >> 2)) ^ swV) << 4)) + ((j & 3) << 2);
    uint32_t hw  = smb + V_OFF + VBUF + e0 * ROWB + colH;
    char* xwr = sm + V_OFF + VBUF + (tid & 31) * ROWB + ((((tid >> 2) & 7)) << 4);
    int vflip = VBUF, wrflip = -VBUF;

    float* h1w = g_h1 + ((size_t)(b0 + e0) * TT) * HD + j;

    float c[4] = {0.f, 0.f, 0.f, 0.f};
    __syncthreads();

    for (int s = 0; s < TT; s++) {
        float4 pinx = make_float4(0.f, 0.f, 0.f, 0.f);
        if (tid < 32 && s + 1 < TT)
            pinx = *(const float4*)(xp + (size_t)(s + 1) * 4);

        u64 A0[4][2];
        ACC_INIT(A0);
        GEMM_G(0, A0, 0); GEMM_G(128, A0, 0);
        GEMM_P(0, 256, A0, 0);                       // chunk kc=16

        u64 A1[4][2];
        ACC_INIT(A1);
        GEMM_G(0, A1, 1024); GEMM_G(128, A1, 1024);
        GEMM_P(0, 256, A1, 1024);

        float h0, h1v, h2, h3;
        UPDATE_P(A0, 0, 0, h0);  UPDATE_P(A0, 1, 1, h1v);
        UPDATE_P(A1, 0, 2, h2);  UPDATE_P(A1, 1, 3, h3);
        STS32(hw, 0, h0);    STS32(hw, 512, h1v);
        STS32(hw, 1024, h2); STS32(hw, 1536, h3);
        h1w[(size_t)s * HD]                       = h0;
        h1w[(size_t)s * HD + (size_t)TT * HD]     = h1v;
        h1w[(size_t)s * HD + (size_t)2 * TT * HD] = h2;
        h1w[(size_t)s * HD + (size_t)3 * TT * HD] = h3;
        if (tid < 32) *(float4*)xwr = pinx;
        __syncthreads();

#pragma unroll
        for (int b = 0; b < 8; b++) va[b] += vflip;
        hw += wrflip; xwr += wrflip;
        vflip = -vflip; wrflip = -wrflip;
    }
}

// ---------------------------------------------------------------------------
extern "C" void kernel_launch(void* const* d_in, const int* in_sizes, int n_in,
                              void* d_out, int out_size)
{
    const float* x    = (const float*)d_in[0];
    const float* Wih0 = (const float*)d_in[1];
    const float* Whh0 = (const float*)d_in[2];
    const float* bih0 = (const float*)d_in[3];
    const float* bhh0 = (const float*)d_in[4];
    const float* Wih1 = (const float*)d_in[5];
    const float* Whh1 = (const float*)d_in[6];
    const float* bih1 = (const float*)d_in[7];
    const float* bhh1 = (const float*)d_in[8];
    const float* Wfc  = (const float*)d_in[9];
    const float* bfc  = (const float*)d_in[10];
    float* out = (float*)d_out;

    cudaFuncSetAttribute(lstm_l0, cudaFuncAttributeMaxDynamicSharedMemorySize, SM_TOTAL);
    cudaFuncSetAttribute(lstm_l1, cudaFuncAttributeMaxDynamicSharedMemorySize, SM_TOTAL);

    dim3 grid(4096 / EC), block(NT);
    lstm_l0<<<grid, block, SM_TOTAL>>>(x, Wih0, Whh0, bih0, bhh0);
    lstm_l1<<<grid, block, SM_TOTAL>>>(Wih1, Whh1, bih1, bhh1, Wfc, bfc, out);
}